// round 2
// baseline (speedup 1.0000x reference)
#include <cuda_runtime.h>

#define N_NODES 65536
#define CF      16
#define L0      4097
#define SFC     2
#define LAT     128
#define HID     512
#define BATCH   16
#define KS      32
#define L1OUT   16385      // conv0 output length
#define NROWS   131104     // SPLIT * SFC = 16*4097*2

// -------- scratch (zero-init .bss, no runtime allocation) --------
__device__ float g_h1[HID * BATCH];                 // [512][16]  (k, b)
__device__ float g_a [SFC * CF * L0 * BATCH];       // [i][ci][l][b]
__device__ float g_c0[SFC * CF * L1OUT * BATCH];    // [i][ci][l][b]
__device__ float g_c1[SFC * N_NODES * BATCH];       // [i][o][b]

// packed dual-FMA: acc(2x f32) += w(2x f32) * x(2x f32)
__device__ __forceinline__ void dfma2(float2 &acc, float2 w, float2 x) {
    asm("{\n\t"
        ".reg .b64 a,b,c;\n\t"
        "mov.b64 a, {%2,%3};\n\t"
        "mov.b64 b, {%4,%5};\n\t"
        "mov.b64 c, {%0,%1};\n\t"
        "fma.rn.f32x2 c, a, b, c;\n\t"
        "mov.b64 {%0,%1}, c;\n\t"
        "}"
        : "+f"(acc.x), "+f"(acc.y)
        : "f"(w.x), "f"(w.y), "f"(x.x), "f"(x.y));
}

// ---------------- Stage 1: h1 = tanh(x @ W1^T + b1) ----------------
// out layout g_h1[j][b], j in [0,512)
__global__ __launch_bounds__(256) void k_gemm1(
    const float* __restrict__ x, const float* __restrict__ W1,
    const float* __restrict__ b1)
{
    __shared__ float xs[BATCH * LAT];
    int tid = threadIdx.x;
    for (int t = tid; t < BATCH * LAT; t += 256) xs[t] = x[t];
    __syncthreads();

    int b = tid & 15;
    int j = blockIdx.x * 16 + (tid >> 4);
    const float4* w4 = (const float4*)(W1 + j * LAT);
    const float4* xv = (const float4*)(xs + b * LAT);
    float acc = 0.f;
#pragma unroll
    for (int c = 0; c < LAT / 4; c++) {
        float4 w = w4[c], xx = xv[c];
        acc += w.x * xx.x + w.y * xx.y + w.z * xx.z + w.w * xx.w;
    }
    g_h1[j * BATCH + b] = tanhf(acc + b1[j]);
}

// ---------------- Stage 2: h2 = tanh(h1 @ W2^T + b2), de-interleaved ----------------
// thread owns 4 rows of W2; h1 staged in shared; FMA2 over batch pairs
__global__ __launch_bounds__(256) void k_gemm2(
    const float* __restrict__ W2, const float* __restrict__ b2)
{
    __shared__ float hs[HID * BATCH];   // [k][b] : 32 KB
    int tid = threadIdx.x;
    for (int t = tid; t < HID * BATCH; t += 256) hs[t] = g_h1[t];
    __syncthreads();

    int base = blockIdx.x * 1024;
    int   r[4]; bool val[4]; size_t off[4];
#pragma unroll
    for (int u = 0; u < 4; u++) {
        r[u]   = base + tid + 256 * u;
        val[u] = r[u] < NROWS;
        off[u] = (size_t)(val[u] ? r[u] : 0) * 128;   // in float4 units (512 floats/row)
    }

    float2 acc[4][8];
#pragma unroll
    for (int u = 0; u < 4; u++)
#pragma unroll
        for (int p = 0; p < 8; p++) acc[u][p] = make_float2(0.f, 0.f);

    const float4* w4 = (const float4*)W2;
    for (int kk = 0; kk < 128; kk++) {
        float4 wv[4];
#pragma unroll
        for (int u = 0; u < 4; u++) wv[u] = w4[off[u] + kk];
#pragma unroll
        for (int j = 0; j < 4; j++) {
            const float4* hp = (const float4*)&hs[(4 * kk + j) * BATCH];
            float4 h0 = hp[0], h1 = hp[1], h2 = hp[2], h3 = hp[3];
            float2 hx[8] = { {h0.x,h0.y},{h0.z,h0.w},{h1.x,h1.y},{h1.z,h1.w},
                             {h2.x,h2.y},{h2.z,h2.w},{h3.x,h3.y},{h3.z,h3.w} };
#pragma unroll
            for (int u = 0; u < 4; u++) {
                float w = ((const float*)&wv[u])[j];
                float2 w2 = make_float2(w, w);
#pragma unroll
                for (int p = 0; p < 8; p++) dfma2(acc[u][p], w2, hx[p]);
            }
        }
    }

#pragma unroll
    for (int u = 0; u < 4; u++) {
        if (!val[u]) continue;
        float bias = b2[r[u]];
        int i = r[u] & 1, rem = r[u] >> 1;
        int c = rem / L0, l = rem - c * L0;
        float* dst = &g_a[(((i * CF + c) * L0) + l) * BATCH];
#pragma unroll
        for (int p = 0; p < 8; p++) {
            float2 v;
            v.x = tanhf(acc[u][p].x + bias);
            v.y = tanhf(acc[u][p].y + bias);
            *(float2*)(dst + 2 * p) = v;
        }
    }
}

// ---------------- Stage 3: ConvTranspose1d #0 (16->16, K=32, s=4, p=16, op=1) + tanh ----------------
// o = 4q + ph ; out[o] = sum_ci sum_s in[ci][q+4-s] * w[ci][co][ph+4s]
// block: 128 thr = co(16) x bp(8); each thread: 4 consecutive q, 4 ph, 2 batches (float2)
__global__ __launch_bounds__(128) void k_conv0(
    const float* __restrict__ ctw0, const float* __restrict__ ctb0)
{
    int i   = blockIdx.y;
    int tid = threadIdx.x;
    __shared__ float ws[CF * CF * 33];   // padded k-stride 33 (bank-conflict free)
    for (int t = tid; t < CF * CF * KS; t += 128) {
        int ci = t >> 9, co = (t >> 5) & 15, k = t & 31;
        ws[(ci * 16 + co) * 33 + k] = ctw0[i * (CF * CF * KS) + t];
    }
    __syncthreads();

    int bp = tid & 7;
    int co = tid >> 3;
    int q0 = blockIdx.x * 4;

    float2 acc[4][4];
#pragma unroll
    for (int j = 0; j < 4; j++)
#pragma unroll
        for (int ph = 0; ph < 4; ph++) acc[j][ph] = make_float2(0.f, 0.f);

#pragma unroll 1
    for (int ci = 0; ci < CF; ci++) {
        const float* src = g_a + (size_t)((i * CF + ci) * L0) * BATCH + 2 * bp;
        float2 inv[11];
#pragma unroll
        for (int t = 0; t < 11; t++) {
            int l = q0 - 3 + t;
            inv[t] = (l >= 0 && l <= L0 - 1) ? *(const float2*)(src + (size_t)l * BATCH)
                                             : make_float2(0.f, 0.f);
        }
        const float* wsp = &ws[(ci * 16 + co) * 33];
        float wr[32];
#pragma unroll
        for (int k = 0; k < 32; k++) wr[k] = wsp[k];

#pragma unroll
        for (int s = 0; s < 8; s++)
#pragma unroll
            for (int ph = 0; ph < 4; ph++) {
                float2 w2 = make_float2(wr[ph + 4 * s], wr[ph + 4 * s]);
#pragma unroll
                for (int j = 0; j < 4; j++) dfma2(acc[j][ph], w2, inv[j + 7 - s]);
            }
    }

    float bias = ctb0[i * CF + co];
#pragma unroll
    for (int j = 0; j < 4; j++)
#pragma unroll
        for (int ph = 0; ph < 4; ph++) {
            int o = 4 * (q0 + j) + ph;
            if (o < L1OUT) {
                float2 v;
                v.x = tanhf(acc[j][ph].x + bias);
                v.y = tanhf(acc[j][ph].y + bias);
                *(float2*)&g_c0[(size_t)((i * CF + co) * L1OUT + o) * BATCH + 2 * bp] = v;
            }
        }
}

// ---------------- Stage 4: ConvTranspose1d #1 (16->1, K=32, s=4, p=16, op=0) + tanh ----------------
// block: 256 thr = qi(32) x bp(8); each thread: 2 consecutive q, 4 ph, 2 batches
__global__ __launch_bounds__(256) void k_conv1(
    const float* __restrict__ ctw1, const float* __restrict__ ctb1)
{
    int i   = blockIdx.y;
    int tid = threadIdx.x;
    __shared__ float wv[CF * KS];
    for (int t = tid; t < CF * KS; t += 256) wv[t] = ctw1[i * (CF * KS) + t];
    __syncthreads();

    int bp = tid & 7;
    int qi = tid >> 3;
    int q  = blockIdx.x * 64 + 2 * qi;

    float2 acc[2][4];
#pragma unroll
    for (int j = 0; j < 2; j++)
#pragma unroll
        for (int ph = 0; ph < 4; ph++) acc[j][ph] = make_float2(0.f, 0.f);

#pragma unroll 1
    for (int ci = 0; ci < CF; ci++) {
        const float* src = g_c0 + (size_t)((i * CF + ci) * L1OUT) * BATCH + 2 * bp;
        float2 inv[9];
#pragma unroll
        for (int t = 0; t < 9; t++) {
            int l = q - 3 + t;
            inv[t] = (l >= 0 && l <= L1OUT - 1) ? *(const float2*)(src + (size_t)l * BATCH)
                                                : make_float2(0.f, 0.f);
        }
        const float* wp = &wv[ci * 32];
#pragma unroll
        for (int s = 0; s < 8; s++)
#pragma unroll
            for (int ph = 0; ph < 4; ph++) {
                float2 w2 = make_float2(wp[ph + 4 * s], wp[ph + 4 * s]);
                dfma2(acc[0][ph], w2, inv[7 - s]);
                dfma2(acc[1][ph], w2, inv[8 - s]);
            }
    }

    float bias = ctb1[i];
#pragma unroll
    for (int j = 0; j < 2; j++)
#pragma unroll
        for (int ph = 0; ph < 4; ph++) {
            int o = 4 * (q + j) + ph;          // always < 65536
            float2 v;
            v.x = tanhf(acc[j][ph].x + bias);
            v.y = tanhf(acc[j][ph].y + bias);
            *(float2*)&g_c1[(size_t)(i * N_NODES + o) * BATCH + 2 * bp] = v;
        }
}

// ---------------- Stage 5: SFC gather + NearestNeighbouring + final combine ----------------
// minus/plus indices are shifted ord indices -> gather ord once with +/-1 halo (clamped)
__global__ __launch_bounds__(256) void k_gather(
    const float* __restrict__ sps_w, const float* __restrict__ sps_b,
    const float* __restrict__ final_w, const float* __restrict__ final_b,
    const float* __restrict__ out_w, const float* __restrict__ out_b,
    const int* __restrict__ ord, float* __restrict__ out)
{
    __shared__ float gs[SFC][258];
    int tid = threadIdx.x;
    int n0  = blockIdx.x * 256;
    int b   = blockIdx.y;

    for (int t = tid; t < SFC * 258; t += 256) {
        int i  = (t >= 258);
        int tt = t - i * 258;
        int n  = n0 - 1 + tt;
        n = n < 0 ? 0 : (n > N_NODES - 1 ? N_NODES - 1 : n);
        int idx = ord[i * N_NODES + n];
        gs[i][tt] = g_c1[(size_t)(i * N_NODES + idx) * BATCH + b];
    }
    __syncthreads();

    int n = n0 + tid;
    float z[SFC];
#pragma unroll
    for (int i = 0; i < SFC; i++) {
        const float* w = &sps_w[(size_t)(i * N_NODES + n) * 3];
        float s = gs[i][tid] * w[0] + gs[i][tid + 1] * w[1] + gs[i][tid + 2] * w[2];
        z[i] = tanhf(s + sps_b[i * N_NODES + n]);
    }
    float zz = tanhf(z[0] * final_w[2 * n] + z[1] * final_w[2 * n + 1] + final_b[n]);
    out[(size_t)b * N_NODES + n] = zz * out_w[n] + out_b[n];
}

// ---------------- launch ----------------
extern "C" void kernel_launch(void* const* d_in, const int* in_sizes, int n_in,
                              void* d_out, int out_size)
{
    const float* x       = (const float*)d_in[0];
    const float* W1      = (const float*)d_in[1];
    const float* b1      = (const float*)d_in[2];
    const float* W2      = (const float*)d_in[3];
    const float* b2      = (const float*)d_in[4];
    const float* ctw0    = (const float*)d_in[5];
    const float* ctb0    = (const float*)d_in[6];
    const float* ctw1    = (const float*)d_in[7];
    const float* ctb1    = (const float*)d_in[8];
    const float* sps_w   = (const float*)d_in[9];
    const float* sps_b   = (const float*)d_in[10];
    const float* final_w = (const float*)d_in[11];
    const float* final_b = (const float*)d_in[12];
    const float* out_w   = (const float*)d_in[13];
    const float* out_b   = (const float*)d_in[14];
    const int*   ord     = (const int*)d_in[15];
    float* out = (float*)d_out;

    k_gemm1<<<32, 256>>>(x, W1, b1);
    k_gemm2<<<(NROWS + 1023) / 1024, 256>>>(W2, b2);
    k_conv0<<<dim3(1025, SFC), 128>>>(ctw0, ctb0);
    k_conv1<<<dim3(256, SFC), 256>>>(ctw1, ctb1);
    k_gather<<<dim3(256, BATCH), 256>>>(sps_w, sps_b, final_w, final_b,
                                        out_w, out_b, ord, out);
}